// round 5
// baseline (speedup 1.0000x reference)
#include <cuda_runtime.h>
#include <math.h>

#define BB 4
#define NN 4096
#define DIMC 1024
#define HEADS 16
#define HD 64
#define DFF 4096
#define WIN 128
#define ROWS (BB * NN)   /* 16384 */

/* ---------------- scratch (static device memory; no allocation) ------------ */
__device__ float g_xnorm[(size_t)ROWS * DIMC];
__device__ float g_qkv[(size_t)ROWS * 3 * DIMC];
__device__ float g_attn[(size_t)ROWS * DIMC];
__device__ float g_x2[(size_t)ROWS * DIMC];
__device__ float g_y[(size_t)ROWS * DIMC];
__device__ float g_h[(size_t)ROWS * DFF];

/* ---------------- f32x2 packed helpers (Blackwell FFMA2) ------------------- */
__device__ __forceinline__ unsigned long long pack2(float lo, float hi) {
    unsigned long long d;
    asm("mov.b64 %0, {%1, %2};"
        : "=l"(d) : "r"(__float_as_uint(lo)), "r"(__float_as_uint(hi)));
    return d;
}
__device__ __forceinline__ void unpack2(unsigned long long v, float &lo, float &hi) {
    unsigned int a, b;
    asm("mov.b64 {%0, %1}, %2;" : "=r"(a), "=r"(b) : "l"(v));
    lo = __uint_as_float(a);
    hi = __uint_as_float(b);
}
__device__ __forceinline__ void fma2(unsigned long long &d,
                                     unsigned long long a,
                                     unsigned long long b) {
    asm("fma.rn.f32x2 %0, %1, %2, %3;" : "=l"(d) : "l"(a), "l"(b), "l"(d));
}

/* ---------------- LayerNorm: one CTA per row (1024 cols) ------------------- */
__global__ void __launch_bounds__(256) ln_kernel(const float *__restrict__ in,
                                                 const float *__restrict__ w,
                                                 const float *__restrict__ b,
                                                 float *__restrict__ out) {
    int row = blockIdx.x;
    int t = threadIdx.x;
    const float4 *x4 = (const float4 *)(in + (size_t)row * DIMC);
    float4 v = x4[t];
    float s = v.x + v.y + v.z + v.w;
    float q = v.x * v.x + v.y * v.y + v.z * v.z + v.w * v.w;
#pragma unroll
    for (int o = 16; o; o >>= 1) {
        s += __shfl_xor_sync(0xffffffffu, s, o);
        q += __shfl_xor_sync(0xffffffffu, q, o);
    }
    __shared__ float ss[8], sq[8];
    if ((t & 31) == 0) { ss[t >> 5] = s; sq[t >> 5] = q; }
    __syncthreads();
    float S = 0.f, Q = 0.f;
#pragma unroll
    for (int i = 0; i < 8; i++) { S += ss[i]; Q += sq[i]; }
    float mean = S * (1.0f / DIMC);
    float var = Q * (1.0f / DIMC) - mean * mean;
    float inv = rsqrtf(var + 1e-5f);
    float4 w4 = ((const float4 *)w)[t];
    float4 b4 = ((const float4 *)b)[t];
    float4 r;
    r.x = (v.x - mean) * inv * w4.x + b4.x;
    r.y = (v.y - mean) * inv * w4.y + b4.y;
    r.z = (v.z - mean) * inv * w4.z + b4.z;
    r.w = (v.w - mean) * inv * w4.w + b4.w;
    ((float4 *)(out + (size_t)row * DIMC))[t] = r;
}

/* ---------------- SGEMM (NT): C = act(A[M,K] @ Bw[N,K]^T + bias) (+res) ---- */
#define BM 128
#define BN 128
#define BKT 32
#define SROW (BM + 4) /* 132: pad to kill bank conflicts, keeps 16B alignment */

template <int GELU, int RES>
__global__ void __launch_bounds__(256) gemm_nt(const float *__restrict__ A,
                                               const float *__restrict__ Bw,
                                               const float *__restrict__ bias,
                                               const float *__restrict__ res,
                                               float *__restrict__ C,
                                               int M, int Nn, int K) {
    __shared__ __align__(16) float As[BKT][SROW];
    __shared__ __align__(16) float Bs[BKT][SROW];
    int tid = threadIdx.x;
    int bm = blockIdx.y * BM;
    int bn = blockIdx.x * BN;
    int tx = tid & 15;  /* n-direction */
    int ty = tid >> 4;  /* m-direction */

    unsigned long long acc[8][4]; /* 8 m-rows x 4 n-pairs (pairs along N) */
#pragma unroll
    for (int i = 0; i < 8; i++)
#pragma unroll
        for (int j = 0; j < 4; j++) acc[i][j] = 0ull;

    int lr = tid >> 3; /* row within 32-row group */
    int lc = tid & 7;  /* float4 index along K-tile */
    const float *Aptr = A + (size_t)(bm + lr) * K + lc * 4;
    const float *Bptr = Bw + (size_t)(bn + lr) * K + lc * 4;

    for (int kt = 0; kt < K; kt += BKT) {
#pragma unroll
        for (int r = 0; r < 4; r++) {
            float4 a = *(const float4 *)(Aptr + (size_t)(r * 32) * K + kt);
            float4 bb = *(const float4 *)(Bptr + (size_t)(r * 32) * K + kt);
            int row = lr + r * 32;
            As[lc * 4 + 0][row] = a.x;
            As[lc * 4 + 1][row] = a.y;
            As[lc * 4 + 2][row] = a.z;
            As[lc * 4 + 3][row] = a.w;
            Bs[lc * 4 + 0][row] = bb.x;
            Bs[lc * 4 + 1][row] = bb.y;
            Bs[lc * 4 + 2][row] = bb.z;
            Bs[lc * 4 + 3][row] = bb.w;
        }
        __syncthreads();
#pragma unroll 8
        for (int k = 0; k < BKT; k++) {
            float4 a0 = *(const float4 *)&As[k][ty * 8];
            float4 a1 = *(const float4 *)&As[k][ty * 8 + 4];
            float4 b0 = *(const float4 *)&Bs[k][tx * 8];
            float4 b1 = *(const float4 *)&Bs[k][tx * 8 + 4];
            unsigned long long bp[4];
            bp[0] = pack2(b0.x, b0.y);
            bp[1] = pack2(b0.z, b0.w);
            bp[2] = pack2(b1.x, b1.y);
            bp[3] = pack2(b1.z, b1.w);
            float av[8] = {a0.x, a0.y, a0.z, a0.w, a1.x, a1.y, a1.z, a1.w};
#pragma unroll
            for (int i = 0; i < 8; i++) {
                unsigned long long a2 = pack2(av[i], av[i]);
#pragma unroll
                for (int j = 0; j < 4; j++) fma2(acc[i][j], a2, bp[j]);
            }
        }
        __syncthreads();
    }

    /* epilogue */
    int gm = bm + ty * 8;
    int gn = bn + tx * 8;
    float bv[8];
    {
        float4 t0 = *(const float4 *)&bias[gn];
        float4 t1 = *(const float4 *)&bias[gn + 4];
        bv[0] = t0.x; bv[1] = t0.y; bv[2] = t0.z; bv[3] = t0.w;
        bv[4] = t1.x; bv[5] = t1.y; bv[6] = t1.z; bv[7] = t1.w;
    }
#pragma unroll
    for (int i = 0; i < 8; i++) {
        float cr[8];
#pragma unroll
        for (int j = 0; j < 4; j++) unpack2(acc[i][j], cr[2 * j], cr[2 * j + 1]);
#pragma unroll
        for (int j = 0; j < 8; j++) {
            float v = cr[j] + bv[j];
            if (GELU) v = 0.5f * v * (1.0f + erff(v * 0.7071067811865475f));
            cr[j] = v;
        }
        size_t off = (size_t)(gm + i) * Nn + gn;
        if (RES) {
            float4 r0 = *(const float4 *)(res + off);
            float4 r1 = *(const float4 *)(res + off + 4);
            cr[0] += r0.x; cr[1] += r0.y; cr[2] += r0.z; cr[3] += r0.w;
            cr[4] += r1.x; cr[5] += r1.y; cr[6] += r1.z; cr[7] += r1.w;
        }
        *(float4 *)(C + off) = make_float4(cr[0], cr[1], cr[2], cr[3]);
        *(float4 *)(C + off + 4) = make_float4(cr[4], cr[5], cr[6], cr[7]);
    }
}

/* ---------------- local attention: 1 CTA = (window block, batch*head) ------ */
/* 128 threads, thread t owns query row t. Online softmax over up to 3 key   */
/* windows (look back/forward 1); out-of-range windows are skipped entirely  */
/* (reference masks whole padded windows).                                   */
#define CHK 64
__global__ void __launch_bounds__(128) attn_kernel(const float *__restrict__ qkv,
                                                   float *__restrict__ out) {
    __shared__ __align__(16) float Ks[CHK][HD];
    __shared__ __align__(16) float Vs[CHK][HD];
    int t = threadIdx.x;
    int blk = blockIdx.x;          /* window block 0..31 */
    int bh = blockIdx.y;           /* 0..63 */
    int b = bh >> 4, h = bh & 15;
    const int nb = NN / WIN;
    size_t rowbase = (size_t)b * NN;
    int qrow = blk * WIN + t;

    const float *qp = qkv + (rowbase + qrow) * (size_t)(3 * DIMC) + h * HD;
    float q[HD];
#pragma unroll
    for (int d = 0; d < HD; d += 4) {
        float4 v = *(const float4 *)(qp + d);
        q[d + 0] = v.x * 0.125f;
        q[d + 1] = v.y * 0.125f;
        q[d + 2] = v.z * 0.125f;
        q[d + 3] = v.w * 0.125f;
    }
    float m = -1e30f, l = 0.f;
    float o[HD];
#pragma unroll
    for (int d = 0; d < HD; d++) o[d] = 0.f;

    int kb0 = (blk - 1 < 0) ? 0 : blk - 1;
    int kb1 = (blk + 1 >= nb) ? nb - 1 : blk + 1;

    for (int kb = kb0; kb <= kb1; kb++) {
        for (int c = 0; c < WIN / CHK; c++) {
            __syncthreads();
            int base_row = kb * WIN + c * CHK;
#pragma unroll
            for (int it = 0; it < 8; it++) {
                int idx = t + it * 128; /* float4 index into 64x64 tile */
                int r = idx >> 4;
                int c4 = idx & 15;
                const float *kp = qkv + (rowbase + base_row + r) * (size_t)(3 * DIMC)
                                  + DIMC + h * HD + c4 * 4;
                *(float4 *)&Ks[r][c4 * 4] = *(const float4 *)kp;
                *(float4 *)&Vs[r][c4 * 4] = *(const float4 *)(kp + DIMC);
            }
            __syncthreads();
#pragma unroll 1
            for (int j = 0; j < CHK; j++) {
                float s = 0.f;
#pragma unroll
                for (int d = 0; d < HD; d += 4) {
                    float4 kv = *(const float4 *)&Ks[j][d];
                    s += q[d] * kv.x + q[d + 1] * kv.y + q[d + 2] * kv.z + q[d + 3] * kv.w;
                }
                if (s <= m) {
                    float p = __expf(s - m);
                    l += p;
#pragma unroll
                    for (int d = 0; d < HD; d += 4) {
                        float4 vv = *(const float4 *)&Vs[j][d];
                        o[d + 0] += p * vv.x;
                        o[d + 1] += p * vv.y;
                        o[d + 2] += p * vv.z;
                        o[d + 3] += p * vv.w;
                    }
                } else {
                    float corr = __expf(m - s);
                    l = l * corr + 1.f;
#pragma unroll
                    for (int d = 0; d < HD; d += 4) {
                        float4 vv = *(const float4 *)&Vs[j][d];
                        o[d + 0] = o[d + 0] * corr + vv.x;
                        o[d + 1] = o[d + 1] * corr + vv.y;
                        o[d + 2] = o[d + 2] * corr + vv.z;
                        o[d + 3] = o[d + 3] * corr + vv.w;
                    }
                    m = s;
                }
            }
        }
    }

    float inv = 1.0f / l;
    float *op = out + (rowbase + qrow) * (size_t)DIMC + h * HD;
#pragma unroll
    for (int d = 0; d < HD; d += 4) {
        *(float4 *)(op + d) =
            make_float4(o[d] * inv, o[d + 1] * inv, o[d + 2] * inv, o[d + 3] * inv);
    }
}

/* ---------------- launch ---------------------------------------------------- */
extern "C" void kernel_launch(void *const *d_in, const int *in_sizes, int n_in,
                              void *d_out, int out_size) {
    const float *x      = (const float *)d_in[0];
    const float *ln1_w  = (const float *)d_in[1];
    const float *ln1_b  = (const float *)d_in[2];
    const float *qkv_w  = (const float *)d_in[3];
    const float *qkv_b  = (const float *)d_in[4];
    const float *proj_w = (const float *)d_in[5];
    const float *proj_b = (const float *)d_in[6];
    const float *ln2_w  = (const float *)d_in[7];
    const float *ln2_b  = (const float *)d_in[8];
    const float *fc1_w  = (const float *)d_in[9];
    const float *fc1_b  = (const float *)d_in[10];
    const float *fc2_w  = (const float *)d_in[11];
    const float *fc2_b  = (const float *)d_in[12];
    float *out = (float *)d_out;

    float *xnorm, *qkvb, *attnb, *x2b, *yb, *hb;
    cudaGetSymbolAddress((void **)&xnorm, g_xnorm);
    cudaGetSymbolAddress((void **)&qkvb, g_qkv);
    cudaGetSymbolAddress((void **)&attnb, g_attn);
    cudaGetSymbolAddress((void **)&x2b, g_x2);
    cudaGetSymbolAddress((void **)&yb, g_y);
    cudaGetSymbolAddress((void **)&hb, g_h);

    /* 1. LN1 */
    ln_kernel<<<ROWS, 256>>>(x, ln1_w, ln1_b, xnorm);
    /* 2. QKV GEMM: [16384,1024] @ [3072,1024]^T */
    gemm_nt<0, 0><<<dim3(3 * DIMC / BN, ROWS / BM), 256>>>(
        xnorm, qkv_w, qkv_b, nullptr, qkvb, ROWS, 3 * DIMC, DIMC);
    /* 3. local attention */
    attn_kernel<<<dim3(NN / WIN, BB * HEADS), 128>>>(qkvb, attnb);
    /* 4. proj GEMM + residual(x) */
    gemm_nt<0, 1><<<dim3(DIMC / BN, ROWS / BM), 256>>>(
        attnb, proj_w, proj_b, x, x2b, ROWS, DIMC, DIMC);
    /* 5. LN2 */
    ln_kernel<<<ROWS, 256>>>(x2b, ln2_w, ln2_b, yb);
    /* 6. FC1 GEMM + GELU */
    gemm_nt<1, 0><<<dim3(DFF / BN, ROWS / BM), 256>>>(
        yb, fc1_w, fc1_b, nullptr, hb, ROWS, DFF, DIMC);
    /* 7. FC2 GEMM + residual(x2) -> out */
    gemm_nt<0, 1><<<dim3(DIMC / BN, ROWS / BM), 256>>>(
        hb, fc2_w, fc2_b, x2b, out, ROWS, DIMC, DFF);
}

// round 10
// speedup vs baseline: 2.7636x; 2.7636x over previous
#include <cuda_runtime.h>
#include <math.h>
#include <stdint.h>

#define BB 4
#define NN 4096
#define DIMC 1024
#define HEADS 16
#define HD 64
#define DFF 4096
#define WIN 128
#define ROWS (BB * NN)   /* 16384 */

/* ---------------- scratch (static device memory; no allocation) ------------ */
__device__ float g_xnorm[(size_t)ROWS * DIMC];
__device__ float g_qkv[(size_t)ROWS * 3 * DIMC];
__device__ float g_attn[(size_t)ROWS * DIMC];
__device__ float g_x2[(size_t)ROWS * DIMC];
__device__ float g_y[(size_t)ROWS * DIMC];
__device__ float g_h[(size_t)ROWS * DFF];
/* tf32-rounded weights */
__device__ float g_wq[(size_t)3 * DIMC * DIMC];
__device__ float g_wp[(size_t)DIMC * DIMC];
__device__ float g_w1[(size_t)DFF * DIMC];
__device__ float g_w2[(size_t)DIMC * DFF];

/* ---------------- helpers -------------------------------------------------- */
__device__ __forceinline__ float tf32r(float x) {
    uint32_t u;
    asm("cvt.rna.tf32.f32 %0, %1;" : "=r"(u) : "f"(x));
    return __uint_as_float(u);
}
__device__ __forceinline__ void cp16(uint32_t dst, const void *src) {
    asm volatile("cp.async.cg.shared.global [%0], [%1], 16;" :: "r"(dst), "l"(src));
}
__device__ __forceinline__ void cp_commit() {
    asm volatile("cp.async.commit_group;" ::: "memory");
}
__device__ __forceinline__ void cp_wait1() {
    asm volatile("cp.async.wait_group 1;" ::: "memory");
}
__device__ __forceinline__ void cp_wait0() {
    asm volatile("cp.async.wait_group 0;" ::: "memory");
}
__device__ __forceinline__ void mma_tf32(float *c, const uint32_t *a, const uint32_t *b) {
    asm volatile(
        "mma.sync.aligned.m16n8k8.row.col.f32.tf32.tf32.f32 "
        "{%0,%1,%2,%3}, {%4,%5,%6,%7}, {%8,%9}, {%0,%1,%2,%3};"
        : "+f"(c[0]), "+f"(c[1]), "+f"(c[2]), "+f"(c[3])
        : "r"(a[0]), "r"(a[1]), "r"(a[2]), "r"(a[3]), "r"(b[0]), "r"(b[1]));
}

/* ---------------- tf32 rounding pass (weights) ----------------------------- */
__global__ void __launch_bounds__(256) round_kernel(const float *__restrict__ in,
                                                    float *__restrict__ out, int n4) {
    int i = blockIdx.x * 256 + threadIdx.x;
    if (i < n4) {
        float4 v = ((const float4 *)in)[i];
        v.x = tf32r(v.x); v.y = tf32r(v.y); v.z = tf32r(v.z); v.w = tf32r(v.w);
        ((float4 *)out)[i] = v;
    }
}

/* ---------------- LayerNorm: one CTA per row (1024 cols) ------------------- */
template <int ROUND>
__global__ void __launch_bounds__(256) ln_kernel(const float *__restrict__ in,
                                                 const float *__restrict__ w,
                                                 const float *__restrict__ b,
                                                 float *__restrict__ out) {
    int row = blockIdx.x;
    int t = threadIdx.x;
    const float4 *x4 = (const float4 *)(in + (size_t)row * DIMC);
    float4 v = x4[t];
    float s = v.x + v.y + v.z + v.w;
    float q = v.x * v.x + v.y * v.y + v.z * v.z + v.w * v.w;
#pragma unroll
    for (int o = 16; o; o >>= 1) {
        s += __shfl_xor_sync(0xffffffffu, s, o);
        q += __shfl_xor_sync(0xffffffffu, q, o);
    }
    __shared__ float ss[8], sq[8];
    if ((t & 31) == 0) { ss[t >> 5] = s; sq[t >> 5] = q; }
    __syncthreads();
    float S = 0.f, Q = 0.f;
#pragma unroll
    for (int i = 0; i < 8; i++) { S += ss[i]; Q += sq[i]; }
    float mean = S * (1.0f / DIMC);
    float var = Q * (1.0f / DIMC) - mean * mean;
    float inv = rsqrtf(var + 1e-5f);
    float4 w4 = ((const float4 *)w)[t];
    float4 b4 = ((const float4 *)b)[t];
    float4 r;
    r.x = (v.x - mean) * inv * w4.x + b4.x;
    r.y = (v.y - mean) * inv * w4.y + b4.y;
    r.z = (v.z - mean) * inv * w4.z + b4.z;
    r.w = (v.w - mean) * inv * w4.w + b4.w;
    if (ROUND) { r.x = tf32r(r.x); r.y = tf32r(r.y); r.z = tf32r(r.z); r.w = tf32r(r.w); }
    ((float4 *)(out + (size_t)row * DIMC))[t] = r;
}

/* ---------------- tf32 mma GEMM (NT): C = act(A@Bw^T + bias) (+res) -------- */
/* 256 thr, CTA 128x128, BK=32, warps 2(m)x4(n) -> 64x32/warp.                */
/* smem: row-major padded tiles, stride 36 floats (144B, 16B-aligned rows).   */
/* layout (floats): A0 @0, A1 @4608, B0 @9216, B1 @13824  (73728 B total)     */
#define GBM 128
#define GBN 128
#define GBK 32
#define AST 36
#define STAGEF 4608
#define GEMM_SMEM 73728

template <int GELU, int RES, int ROUND>
__global__ void __launch_bounds__(256, 2) mma_gemm(const float *__restrict__ A,
                                                   const float *__restrict__ Bw,
                                                   const float *__restrict__ bias,
                                                   const float *__restrict__ res,
                                                   float *__restrict__ C,
                                                   int M, int Nn, int K) {
    extern __shared__ float smem[];
    int tid = threadIdx.x;
    int l = tid & 31, w = tid >> 5;
    int wm = w >> 2, wn = w & 3;
    int qr = l >> 2, qc = l & 3;
    int bm = blockIdx.y * GBM, bn = blockIdx.x * GBN;

    /* loader mapping: thread covers rows lr+32r (r=0..3), 16B chunk lc */
    int lr = tid >> 3;   /* 0..31 */
    int lc = tid & 7;    /* float4 along k */
    uint32_t sbase = (uint32_t)__cvta_generic_to_shared(smem);
    uint32_t uA = sbase + (uint32_t)(lr * (AST * 4) + lc * 16);
    uint32_t uB = uA + 36864u;
    const float *gA = A + (size_t)(bm + lr) * K + lc * 4;
    const float *gB = Bw + (size_t)(bn + lr) * K + lc * 4;

    float acc[4][4][4];
#pragma unroll
    for (int i = 0; i < 4; i++)
#pragma unroll
        for (int j = 0; j < 4; j++)
#pragma unroll
            for (int k = 0; k < 4; k++) acc[i][j][k] = 0.f;

    const int nkt = K / GBK;

    /* prologue: tile 0 -> stage 0 */
#pragma unroll
    for (int r = 0; r < 4; r++) {
        cp16(uA + r * 4608u, gA + (size_t)r * 32 * K);
        cp16(uB + r * 4608u, gB + (size_t)r * 32 * K);
    }
    cp_commit();

    for (int kt = 0; kt < nkt; kt++) {
        if (kt + 1 < nkt) {
            uint32_t so = ((kt + 1) & 1) * 18432u;
            const float *pa = gA + (kt + 1) * 32;
            const float *pb = gB + (kt + 1) * 32;
#pragma unroll
            for (int r = 0; r < 4; r++) {
                cp16(uA + so + r * 4608u, pa + (size_t)r * 32 * K);
                cp16(uB + so + r * 4608u, pb + (size_t)r * 32 * K);
            }
            cp_commit();
            cp_wait1();
        } else {
            cp_wait0();
        }
        __syncthreads();

        const float *As = smem + (kt & 1) * STAGEF;
        const float *Bs = smem + 2 * STAGEF + (kt & 1) * STAGEF;
#pragma unroll
        for (int kk = 0; kk < 4; kk++) {
            int col0 = kk * 8 + qc;
            uint32_t af[4][4];
#pragma unroll
            for (int i = 0; i < 4; i++) {
                int m0 = wm * 64 + i * 16 + qr;
                af[i][0] = __float_as_uint(As[m0 * AST + col0]);
                af[i][1] = __float_as_uint(As[(m0 + 8) * AST + col0]);
                af[i][2] = __float_as_uint(As[m0 * AST + col0 + 4]);
                af[i][3] = __float_as_uint(As[(m0 + 8) * AST + col0 + 4]);
            }
            uint32_t bf[4][2];
#pragma unroll
            for (int j = 0; j < 4; j++) {
                int n0 = wn * 32 + j * 8 + qr;
                bf[j][0] = __float_as_uint(Bs[n0 * AST + col0]);
                bf[j][1] = __float_as_uint(Bs[n0 * AST + col0 + 4]);
            }
#pragma unroll
            for (int i = 0; i < 4; i++)
#pragma unroll
                for (int j = 0; j < 4; j++) mma_tf32(acc[i][j], af[i], bf[j]);
        }
        __syncthreads();
    }

    /* epilogue: c0,c1 @ (row0, 2qc..2qc+1); c2,c3 @ (row0+8, ...) */
#pragma unroll
    for (int i = 0; i < 4; i++) {
        int row0 = bm + wm * 64 + i * 16 + qr;
#pragma unroll
        for (int j = 0; j < 4; j++) {
            int col = bn + wn * 32 + j * 8 + qc * 2;
            float b0 = bias[col], b1 = bias[col + 1];
            float v0 = acc[i][j][0] + b0;
            float v1 = acc[i][j][1] + b1;
            float v2 = acc[i][j][2] + b0;
            float v3 = acc[i][j][3] + b1;
            if (GELU) {
                v0 = 0.5f * v0 * (1.0f + erff(v0 * 0.7071067811865475f));
                v1 = 0.5f * v1 * (1.0f + erff(v1 * 0.7071067811865475f));
                v2 = 0.5f * v2 * (1.0f + erff(v2 * 0.7071067811865475f));
                v3 = 0.5f * v3 * (1.0f + erff(v3 * 0.7071067811865475f));
            }
            size_t o0 = (size_t)row0 * Nn + col;
            size_t o1 = (size_t)(row0 + 8) * Nn + col;
            if (RES) {
                float2 r0 = *(const float2 *)(res + o0);
                float2 r1 = *(const float2 *)(res + o1);
                v0 += r0.x; v1 += r0.y; v2 += r1.x; v3 += r1.y;
            }
            if (ROUND) { v0 = tf32r(v0); v1 = tf32r(v1); v2 = tf32r(v2); v3 = tf32r(v3); }
            *(float2 *)(C + o0) = make_float2(v0, v1);
            *(float2 *)(C + o1) = make_float2(v2, v3);
        }
    }
}

/* ---------------- local attention: 1 CTA = (window block, batch*head) ------ */
#define CHK 64
__global__ void __launch_bounds__(128) attn_kernel(const float *__restrict__ qkv,
                                                   float *__restrict__ out) {
    __shared__ __align__(16) float Ks[CHK][HD];
    __shared__ __align__(16) float Vs[CHK][HD];
    int t = threadIdx.x;
    int blk = blockIdx.x;
    int bh = blockIdx.y;
    int b = bh >> 4, h = bh & 15;
    const int nb = NN / WIN;
    size_t rowbase = (size_t)b * NN;
    int qrow = blk * WIN + t;

    const float *qp = qkv + (rowbase + qrow) * (size_t)(3 * DIMC) + h * HD;
    float q[HD];
#pragma unroll
    for (int d = 0; d < HD; d += 4) {
        float4 v = *(const float4 *)(qp + d);
        q[d + 0] = v.x * 0.125f;
        q[d + 1] = v.y * 0.125f;
        q[d + 2] = v.z * 0.125f;
        q[d + 3] = v.w * 0.125f;
    }
    float m = -1e30f, lsum = 0.f;
    float o[HD];
#pragma unroll
    for (int d = 0; d < HD; d++) o[d] = 0.f;

    int kb0 = (blk - 1 < 0) ? 0 : blk - 1;
    int kb1 = (blk + 1 >= nb) ? nb - 1 : blk + 1;

    for (int kb = kb0; kb <= kb1; kb++) {
        for (int c = 0; c < WIN / CHK; c++) {
            __syncthreads();
            int base_row = kb * WIN + c * CHK;
#pragma unroll
            for (int it = 0; it < 8; it++) {
                int idx = t + it * 128;
                int r = idx >> 4;
                int c4 = idx & 15;
                const float *kp = qkv + (rowbase + base_row + r) * (size_t)(3 * DIMC)
                                  + DIMC + h * HD + c4 * 4;
                *(float4 *)&Ks[r][c4 * 4] = *(const float4 *)kp;
                *(float4 *)&Vs[r][c4 * 4] = *(const float4 *)(kp + DIMC);
            }
            __syncthreads();
#pragma unroll 1
            for (int j = 0; j < CHK; j++) {
                float s = 0.f;
#pragma unroll
                for (int d = 0; d < HD; d += 4) {
                    float4 kv = *(const float4 *)&Ks[j][d];
                    s += q[d] * kv.x + q[d + 1] * kv.y + q[d + 2] * kv.z + q[d + 3] * kv.w;
                }
                if (s <= m) {
                    float p = __expf(s - m);
                    lsum += p;
#pragma unroll
                    for (int d = 0; d < HD; d += 4) {
                        float4 vv = *(const float4 *)&Vs[j][d];
                        o[d + 0] += p * vv.x;
                        o[d + 1] += p * vv.y;
                        o[d + 2] += p * vv.z;
                        o[d + 3] += p * vv.w;
                    }
                } else {
                    float corr = __expf(m - s);
                    lsum = lsum * corr + 1.f;
#pragma unroll
                    for (int d = 0; d < HD; d += 4) {
                        float4 vv = *(const float4 *)&Vs[j][d];
                        o[d + 0] = o[d + 0] * corr + vv.x;
                        o[d + 1] = o[d + 1] * corr + vv.y;
                        o[d + 2] = o[d + 2] * corr + vv.z;
                        o[d + 3] = o[d + 3] * corr + vv.w;
                    }
                    m = s;
                }
            }
        }
    }

    float inv = 1.0f / lsum;
    float *op = out + (rowbase + qrow) * (size_t)DIMC + h * HD;
#pragma unroll
    for (int d = 0; d < HD; d += 4) {
        *(float4 *)(op + d) = make_float4(tf32r(o[d] * inv), tf32r(o[d + 1] * inv),
                                          tf32r(o[d + 2] * inv), tf32r(o[d + 3] * inv));
    }
}

/* ---------------- launch ---------------------------------------------------- */
extern "C" void kernel_launch(void *const *d_in, const int *in_sizes, int n_in,
                              void *d_out, int out_size) {
    const float *x      = (const float *)d_in[0];
    const float *ln1_w  = (const float *)d_in[1];
    const float *ln1_b  = (const float *)d_in[2];
    const float *qkv_w  = (const float *)d_in[3];
    const float *qkv_b  = (const float *)d_in[4];
    const float *proj_w = (const float *)d_in[5];
    const float *proj_b = (const float *)d_in[6];
    const float *ln2_w  = (const float *)d_in[7];
    const float *ln2_b  = (const float *)d_in[8];
    const float *fc1_w  = (const float *)d_in[9];
    const float *fc1_b  = (const float *)d_in[10];
    const float *fc2_w  = (const float *)d_in[11];
    const float *fc2_b  = (const float *)d_in[12];
    float *out = (float *)d_out;

    float *xnorm, *qkvb, *attnb, *x2b, *yb, *hb, *wq, *wp, *w1, *w2;
    cudaGetSymbolAddress((void **)&xnorm, g_xnorm);
    cudaGetSymbolAddress((void **)&qkvb, g_qkv);
    cudaGetSymbolAddress((void **)&attnb, g_attn);
    cudaGetSymbolAddress((void **)&x2b, g_x2);
    cudaGetSymbolAddress((void **)&yb, g_y);
    cudaGetSymbolAddress((void **)&hb, g_h);
    cudaGetSymbolAddress((void **)&wq, g_wq);
    cudaGetSymbolAddress((void **)&wp, g_wp);
    cudaGetSymbolAddress((void **)&w1, g_w1);
    cudaGetSymbolAddress((void **)&w2, g_w2);

    cudaFuncSetAttribute(mma_gemm<0, 0, 0>, cudaFuncAttributeMaxDynamicSharedMemorySize, GEMM_SMEM);
    cudaFuncSetAttribute(mma_gemm<0, 1, 0>, cudaFuncAttributeMaxDynamicSharedMemorySize, GEMM_SMEM);
    cudaFuncSetAttribute(mma_gemm<1, 0, 1>, cudaFuncAttributeMaxDynamicSharedMemorySize, GEMM_SMEM);

    /* 0. weight rounding to tf32 (RN) */
    {
        int n;
        n = 3 * DIMC * DIMC / 4; round_kernel<<<(n + 255) / 256, 256>>>(qkv_w, wq, n);
        n = DIMC * DIMC / 4;     round_kernel<<<(n + 255) / 256, 256>>>(proj_w, wp, n);
        n = DFF * DIMC / 4;      round_kernel<<<(n + 255) / 256, 256>>>(fc1_w, w1, n);
        n = DIMC * DFF / 4;      round_kernel<<<(n + 255) / 256, 256>>>(fc2_w, w2, n);
    }
    /* 1. LN1 (tf32-rounded output) */
    ln_kernel<1><<<ROWS, 256>>>(x, ln1_w, ln1_b, xnorm);
    /* 2. QKV GEMM: [16384,1024] @ [3072,1024]^T */
    mma_gemm<0, 0, 0><<<dim3(3 * DIMC / GBN, ROWS / GBM), 256, GEMM_SMEM>>>(
        xnorm, wq, qkv_b, nullptr, qkvb, ROWS, 3 * DIMC, DIMC);
    /* 3. local attention (tf32-rounded output) */
    attn_kernel<<<dim3(NN / WIN, BB * HEADS), 128>>>(qkvb, attnb);
    /* 4. proj GEMM + residual(x) */
    mma_gemm<0, 1, 0><<<dim3(DIMC / GBN, ROWS / GBM), 256, GEMM_SMEM>>>(
        attnb, wp, proj_b, x, x2b, ROWS, DIMC, DIMC);
    /* 5. LN2 (tf32-rounded output) */
    ln_kernel<1><<<ROWS, 256>>>(x2b, ln2_w, ln2_b, yb);
    /* 6. FC1 GEMM + GELU (tf32-rounded output) */
    mma_gemm<1, 0, 1><<<dim3(DFF / GBN, ROWS / GBM), 256, GEMM_SMEM>>>(
        yb, w1, fc1_b, nullptr, hb, ROWS, DFF, DIMC);
    /* 7. FC2 GEMM + residual(x2) -> out */
    mma_gemm<0, 1, 0><<<dim3(DIMC / GBN, ROWS / GBM), 256, GEMM_SMEM>>>(
        hb, w2, fc2_b, x2b, out, ROWS, DIMC, DFF);
}

// round 12
// speedup vs baseline: 3.8314x; 1.3864x over previous
#include <cuda_runtime.h>
#include <cuda_fp16.h>
#include <math.h>
#include <stdint.h>

#define BB 4
#define NN 4096
#define DIMC 1024
#define HEADS 16
#define HD 64
#define DFF 4096
#define WIN 128
#define ROWS (BB * NN)   /* 16384 */

/* ---------------- scratch (static device memory; no allocation) ------------ */
__device__ float g_qkv[(size_t)ROWS * 3 * DIMC];
__device__ float g_x2[(size_t)ROWS * DIMC];
__device__ __half h_xn[(size_t)ROWS * DIMC];
__device__ __half h_attn[(size_t)ROWS * DIMC];
__device__ __half h_y[(size_t)ROWS * DIMC];
__device__ __half h_h[(size_t)ROWS * DFF];
__device__ __half h_wq[(size_t)3 * DIMC * DIMC];
__device__ __half h_wp[(size_t)DIMC * DIMC];
__device__ __half h_w1[(size_t)DFF * DIMC];
__device__ __half h_w2[(size_t)DIMC * DFF];

/* ---------------- helpers -------------------------------------------------- */
__device__ __forceinline__ void cp16(uint32_t dst, const void *src) {
    asm volatile("cp.async.cg.shared.global [%0], [%1], 16;" :: "r"(dst), "l"(src));
}
__device__ __forceinline__ void cp_commit() {
    asm volatile("cp.async.commit_group;" ::: "memory");
}
__device__ __forceinline__ void cp_wait1() {
    asm volatile("cp.async.wait_group 1;" ::: "memory");
}
__device__ __forceinline__ void cp_wait0() {
    asm volatile("cp.async.wait_group 0;" ::: "memory");
}
__device__ __forceinline__ void mma_f16(float *c, const uint32_t *a, const uint32_t *b) {
    asm volatile(
        "mma.sync.aligned.m16n8k16.row.col.f32.f16.f16.f32 "
        "{%0,%1,%2,%3}, {%4,%5,%6,%7}, {%8,%9}, {%0,%1,%2,%3};"
        : "+f"(c[0]), "+f"(c[1]), "+f"(c[2]), "+f"(c[3])
        : "r"(a[0]), "r"(a[1]), "r"(a[2]), "r"(a[3]), "r"(b[0]), "r"(b[1]));
}

/* ---------------- fp32 -> fp16 convert pass (weights) ---------------------- */
__global__ void __launch_bounds__(256) cvt_kernel(const float *__restrict__ in,
                                                  __half *__restrict__ out, int n4) {
    int i = blockIdx.x * 256 + threadIdx.x;
    if (i < n4) {
        float4 v = ((const float4 *)in)[i];
        __half2 a = __floats2half2_rn(v.x, v.y);
        __half2 b = __floats2half2_rn(v.z, v.w);
        __half2 *op = (__half2 *)(out + (size_t)i * 4);
        op[0] = a;
        op[1] = b;
    }
}

/* ---------------- LayerNorm: one CTA per row (1024 cols), half output ------ */
__global__ void __launch_bounds__(256) ln_kernel(const float *__restrict__ in,
                                                 const float *__restrict__ w,
                                                 const float *__restrict__ b,
                                                 __half *__restrict__ out) {
    int row = blockIdx.x;
    int t = threadIdx.x;
    const float4 *x4 = (const float4 *)(in + (size_t)row * DIMC);
    float4 v = x4[t];
    float s = v.x + v.y + v.z + v.w;
    float q = v.x * v.x + v.y * v.y + v.z * v.z + v.w * v.w;
#pragma unroll
    for (int o = 16; o; o >>= 1) {
        s += __shfl_xor_sync(0xffffffffu, s, o);
        q += __shfl_xor_sync(0xffffffffu, q, o);
    }
    __shared__ float ss[8], sq[8];
    if ((t & 31) == 0) { ss[t >> 5] = s; sq[t >> 5] = q; }
    __syncthreads();
    float S = 0.f, Q = 0.f;
#pragma unroll
    for (int i = 0; i < 8; i++) { S += ss[i]; Q += sq[i]; }
    float mean = S * (1.0f / DIMC);
    float var = Q * (1.0f / DIMC) - mean * mean;
    float inv = rsqrtf(var + 1e-5f);
    float4 w4 = ((const float4 *)w)[t];
    float4 b4 = ((const float4 *)b)[t];
    __half2 r0 = __floats2half2_rn((v.x - mean) * inv * w4.x + b4.x,
                                   (v.y - mean) * inv * w4.y + b4.y);
    __half2 r1 = __floats2half2_rn((v.z - mean) * inv * w4.z + b4.z,
                                   (v.w - mean) * inv * w4.w + b4.w);
    __half2 *op = (__half2 *)(out + (size_t)row * DIMC + t * 4);
    op[0] = r0;
    op[1] = r1;
}

/* ---------------- fp16 mma GEMM (NT): C = act(A@Bw^T + bias) (+res) -------- */
/* 256 thr, CTA 128x128, BK=32 halfs, warps 2(m)x4(n) -> 64x32/warp.          */
/* smem tiles: row-major halfs, stride 40 (80B rows, 16B-aligned).            */
/* bytes: A stage 10240; A0@0 A1@10240 B0@20480 B1@30720; total 40960.        */
#define GBM 128
#define GBN 128
#define GBK 32
#define HSTRIDE 40                 /* halfs per row */
#define HROWB 80                   /* bytes per row */
#define STAGEB 10240
#define GEMM_SMEM 40960

template <int GELU, int RES, int OUTH>
__global__ void __launch_bounds__(256, 2) mma_gemm(const __half *__restrict__ A,
                                                   const __half *__restrict__ Bw,
                                                   const float *__restrict__ bias,
                                                   const float *__restrict__ res,
                                                   void *__restrict__ Cv,
                                                   int M, int Nn, int K) {
    extern __shared__ __align__(16) char smem[];
    int tid = threadIdx.x;
    int l = tid & 31, w = tid >> 5;
    int wm = w >> 2, wn = w & 3;
    int qr = l >> 2, qc = l & 3;
    int bm = blockIdx.y * GBM, bn = blockIdx.x * GBN;

    /* loader: thread -> rows lr, lr+64; 16B chunk c (8 halfs) of the 64B row */
    int lr = tid >> 2;   /* 0..63 */
    int c = tid & 3;
    uint32_t sbase = (uint32_t)__cvta_generic_to_shared(smem);
    uint32_t uA = sbase + (uint32_t)(lr * HROWB + c * 16);
    uint32_t uB = uA + 20480u;
    const __half *gA = A + (size_t)(bm + lr) * K + c * 8;
    const __half *gB = Bw + (size_t)(bn + lr) * K + c * 8;

    float acc[4][4][4];
#pragma unroll
    for (int i = 0; i < 4; i++)
#pragma unroll
        for (int j = 0; j < 4; j++)
#pragma unroll
            for (int k = 0; k < 4; k++) acc[i][j][k] = 0.f;

    const int nkt = K / GBK;

    /* prologue: k-tile 0 -> stage 0 */
#pragma unroll
    for (int r = 0; r < 2; r++) {
        cp16(uA + r * (64u * HROWB), gA + (size_t)r * 64 * K);
        cp16(uB + r * (64u * HROWB), gB + (size_t)r * 64 * K);
    }
    cp_commit();

    for (int kt = 0; kt < nkt; kt++) {
        if (kt + 1 < nkt) {
            uint32_t so = ((kt + 1) & 1) * (uint32_t)STAGEB;
            const __half *pa = gA + (kt + 1) * GBK;
            const __half *pb = gB + (kt + 1) * GBK;
#pragma unroll
            for (int r = 0; r < 2; r++) {
                cp16(uA + so + r * (64u * HROWB), pa + (size_t)r * 64 * K);
                cp16(uB + so + r * (64u * HROWB), pb + (size_t)r * 64 * K);
            }
            cp_commit();
            cp_wait1();
        } else {
            cp_wait0();
        }
        __syncthreads();

        const uint32_t *As = (const uint32_t *)(smem + (kt & 1) * STAGEB);
        const uint32_t *Bs = (const uint32_t *)(smem + 20480 + (kt & 1) * STAGEB);
#pragma unroll
        for (int kk = 0; kk < 2; kk++) {
            int cw = kk * 8 + qc;              /* word (=2-half) offset along k */
            uint32_t af[4][4];
#pragma unroll
            for (int i = 0; i < 4; i++) {
                int m0 = wm * 64 + i * 16 + qr;
                af[i][0] = As[m0 * 20 + cw];
                af[i][1] = As[(m0 + 8) * 20 + cw];
                af[i][2] = As[m0 * 20 + cw + 4];
                af[i][3] = As[(m0 + 8) * 20 + cw + 4];
            }
            uint32_t bf[4][2];
#pragma unroll
            for (int j = 0; j < 4; j++) {
                int n0 = wn * 32 + j * 8 + qr;
                bf[j][0] = Bs[n0 * 20 + cw];
                bf[j][1] = Bs[n0 * 20 + cw + 4];
            }
#pragma unroll
            for (int i = 0; i < 4; i++)
#pragma unroll
                for (int j = 0; j < 4; j++) mma_f16(acc[i][j], af[i], bf[j]);
        }
        __syncthreads();
    }

    /* epilogue: c0,c1 @ (row0, col..col+1); c2,c3 @ (row0+8, ...) */
#pragma unroll
    for (int i = 0; i < 4; i++) {
        int row0 = bm + wm * 64 + i * 16 + qr;
#pragma unroll
        for (int j = 0; j < 4; j++) {
            int col = bn + wn * 32 + j * 8 + qc * 2;
            float b0 = bias[col], b1 = bias[col + 1];
            float v0 = acc[i][j][0] + b0;
            float v1 = acc[i][j][1] + b1;
            float v2 = acc[i][j][2] + b0;
            float v3 = acc[i][j][3] + b1;
            if (GELU) {
                v0 = 0.5f * v0 * (1.0f + erff(v0 * 0.7071067811865475f));
                v1 = 0.5f * v1 * (1.0f + erff(v1 * 0.7071067811865475f));
                v2 = 0.5f * v2 * (1.0f + erff(v2 * 0.7071067811865475f));
                v3 = 0.5f * v3 * (1.0f + erff(v3 * 0.7071067811865475f));
            }
            size_t o0 = (size_t)row0 * Nn + col;
            size_t o1 = (size_t)(row0 + 8) * Nn + col;
            if (RES) {
                float2 r0 = *(const float2 *)(res + o0);
                float2 r1 = *(const float2 *)(res + o1);
                v0 += r0.x; v1 += r0.y; v2 += r1.x; v3 += r1.y;
            }
            if (OUTH) {
                __half *Ch = (__half *)Cv;
                *(__half2 *)(Ch + o0) = __floats2half2_rn(v0, v1);
                *(__half2 *)(Ch + o1) = __floats2half2_rn(v2, v3);
            } else {
                float *Cf = (float *)Cv;
                *(float2 *)(Cf + o0) = make_float2(v0, v1);
                *(float2 *)(Cf + o1) = make_float2(v2, v3);
            }
        }
    }
}

/* ---------------- local attention: 1 CTA = (window block, batch*head) ------ */
#define CHK 64
__global__ void __launch_bounds__(128) attn_kernel(const float *__restrict__ qkv,
                                                   __half *__restrict__ out) {
    __shared__ __align__(16) float Ks[CHK][HD];
    __shared__ __align__(16) float Vs[CHK][HD];
    int t = threadIdx.x;
    int blk = blockIdx.x;
    int bh = blockIdx.y;
    int b = bh >> 4, h = bh & 15;
    const int nb = NN / WIN;
    size_t rowbase = (size_t)b * NN;
    int qrow = blk * WIN + t;

    const float *qp = qkv + (rowbase + qrow) * (size_t)(3 * DIMC) + h * HD;
    float q[HD];
#pragma unroll
    for (int d = 0; d < HD; d += 4) {
        float4 v = *(const float4 *)(qp + d);
        q[d + 0] = v.x * 0.125f;
        q[d + 1] = v.y * 0.125f;
        q[d + 2] = v.z * 0.125f;
        q[d + 3] = v.w * 0.125f;
    }
    float m = -1e30f, lsum = 0.f;
    float o[HD];
#pragma unroll
    for (int d = 0; d < HD; d++) o[d] = 0.f;

    int kb0 = (blk - 1 < 0) ? 0 : blk - 1;
    int kb1 = (blk + 1 >= nb) ? nb - 1 : blk + 1;

    for (int kb = kb0; kb <= kb1; kb++) {
        for (int c = 0; c < WIN / CHK; c++) {
            __syncthreads();
            int base_row = kb * WIN + c * CHK;
#pragma unroll
            for (int it = 0; it < 8; it++) {
                int idx = t + it * 128;
                int r = idx >> 4;
                int c4 = idx & 15;
                const float *kp = qkv + (rowbase + base_row + r) * (size_t)(3 * DIMC)
                                  + DIMC + h * HD + c4 * 4;
                *(float4 *)&Ks[r][c4 * 4] = *(const float4 *)kp;
                *(float4 *)&Vs[r][c4 * 4] = *(const float4 *)(kp + DIMC);
            }
            __syncthreads();
#pragma unroll 1
            for (int j = 0; j < CHK; j++) {
                float s = 0.f;
#pragma unroll
                for (int d = 0; d < HD; d += 4) {
                    float4 kv = *(const float4 *)&Ks[j][d];
                    s += q[d] * kv.x + q[d + 1] * kv.y + q[d + 2] * kv.z + q[d + 3] * kv.w;
                }
                if (s <= m) {
                    float p = __expf(s - m);
                    lsum += p;
#pragma unroll
                    for (int d = 0; d < HD; d += 4) {
                        float4 vv = *(const float4 *)&Vs[j][d];
                        o[d + 0] += p * vv.x;
                        o[d + 1] += p * vv.y;
                        o[d + 2] += p * vv.z;
                        o[d + 3] += p * vv.w;
                    }
                } else {
                    float corr = __expf(m - s);
                    lsum = lsum * corr + 1.f;
#pragma unroll
                    for (int d = 0; d < HD; d += 4) {
                        float4 vv = *(const float4 *)&Vs[j][d];
                        o[d + 0] = o[d + 0] * corr + vv.x;
                        o[d + 1] = o[d + 1] * corr + vv.y;
                        o[d + 2] = o[d + 2] * corr + vv.z;
                        o[d + 3] = o[d + 3] * corr + vv.w;
                    }
                    m = s;
                }
            }
        }
    }

    float inv = 1.0f / lsum;
    __half *op = out + (rowbase + qrow) * (size_t)DIMC + h * HD;
#pragma unroll
    for (int d = 0; d < HD; d += 4) {
        *(__half2 *)(op + d) = __floats2half2_rn(o[d] * inv, o[d + 1] * inv);
        *(__half2 *)(op + d + 2) = __floats2half2_rn(o[d + 2] * inv, o[d + 3] * inv);
    }
}

/* ---------------- launch ---------------------------------------------------- */
extern "C" void kernel_launch(void *const *d_in, const int *in_sizes, int n_in,
                              void *d_out, int out_size) {
    const float *x      = (const float *)d_in[0];
    const float *ln1_w  = (const float *)d_in[1];
    const float *ln1_b  = (const float *)d_in[2];
    const float *qkv_w  = (const float *)d_in[3];
    const float *qkv_b  = (const float *)d_in[4];
    const float *proj_w = (const float *)d_in[5];
    const float *proj_b = (const float *)d_in[6];
    const float *ln2_w  = (const float *)d_in[7];
    const float *ln2_b  = (const float *)d_in[8];
    const float *fc1_w  = (const float *)d_in[9];
    const float *fc1_b  = (const float *)d_in[10];
    const float *fc2_w  = (const float *)d_in[11];
    const float *fc2_b  = (const float *)d_in[12];
    float *out = (float *)d_out;

    float *qkvb, *x2b;
    __half *xnh, *attnh, *yh, *hh, *wq, *wp, *w1, *w2;
    cudaGetSymbolAddress((void **)&qkvb, g_qkv);
    cudaGetSymbolAddress((void **)&x2b, g_x2);
    cudaGetSymbolAddress((void **)&xnh, h_xn);
    cudaGetSymbolAddress((void **)&attnh, h_attn);
    cudaGetSymbolAddress((void **)&yh, h_y);
    cudaGetSymbolAddress((void **)&hh, h_h);
    cudaGetSymbolAddress((void **)&wq, h_wq);
    cudaGetSymbolAddress((void **)&wp, h_wp);
    cudaGetSymbolAddress((void **)&w1, h_w1);
    cudaGetSymbolAddress((void **)&w2, h_w2);

    cudaFuncSetAttribute(mma_gemm<0, 0, 0>, cudaFuncAttributeMaxDynamicSharedMemorySize, GEMM_SMEM);
    cudaFuncSetAttribute(mma_gemm<0, 1, 0>, cudaFuncAttributeMaxDynamicSharedMemorySize, GEMM_SMEM);
    cudaFuncSetAttribute(mma_gemm<1, 0, 1>, cudaFuncAttributeMaxDynamicSharedMemorySize, GEMM_SMEM);

    /* 0. weight conversion to fp16 (RN) */
    {
        int n;
        n = 3 * DIMC * DIMC / 4; cvt_kernel<<<(n + 255) / 256, 256>>>(qkv_w, wq, n);
        n = DIMC * DIMC / 4;     cvt_kernel<<<(n + 255) / 256, 256>>>(proj_w, wp, n);
        n = DFF * DIMC / 4;      cvt_kernel<<<(n + 255) / 256, 256>>>(fc1_w, w1, n);
        n = DIMC * DFF / 4;      cvt_kernel<<<(n + 255) / 256, 256>>>(fc2_w, w2, n);
    }
    /* 1. LN1 -> fp16 */
    ln_kernel<<<ROWS, 256>>>(x, ln1_w, ln1_b, xnh);
    /* 2. QKV GEMM: [16384,1024] @ [3072,1024]^T -> fp32 */
    mma_gemm<0, 0, 0><<<dim3(3 * DIMC / GBN, ROWS / GBM), 256, GEMM_SMEM>>>(
        xnh, wq, qkv_b, nullptr, qkvb, ROWS, 3 * DIMC, DIMC);
    /* 3. local attention -> fp16 */
    attn_kernel<<<dim3(NN / WIN, BB * HEADS), 128>>>(qkvb, attnh);
    /* 4. proj GEMM + residual(x) -> fp32 */
    mma_gemm<0, 1, 0><<<dim3(DIMC / GBN, ROWS / GBM), 256, GEMM_SMEM>>>(
        attnh, wp, proj_b, x, x2b, ROWS, DIMC, DIMC);
    /* 5. LN2 -> fp16 */
    ln_kernel<<<ROWS, 256>>>(x2b, ln2_w, ln2_b, yh);
    /* 6. FC1 GEMM + GELU -> fp16 */
    mma_gemm<1, 0, 1><<<dim3(DFF / GBN, ROWS / GBM), 256, GEMM_SMEM>>>(
        yh, w1, fc1_b, nullptr, hh, ROWS, DFF, DIMC);
    /* 7. FC2 GEMM + residual(x2) -> fp32 out */
    mma_gemm<0, 1, 0><<<dim3(DIMC / GBN, ROWS / GBM), 256, GEMM_SMEM>>>(
        hh, w2, fc2_b, x2b, out, ROWS, DIMC, DFF);
}